// round 1
// baseline (speedup 1.0000x reference)
#include <cuda_runtime.h>
#include <math.h>

#define B_SZ 4
#define SEQ  2048
#define DIM  1024
#define NH   16
#define HD   64
#define D3   3072
#define M_TOT (B_SZ * SEQ)

// Scratch (device globals — no runtime allocation allowed)
__device__ float g_qkv[(size_t)M_TOT * D3];   // [B*L, 3*DIM]
__device__ float g_att[(size_t)M_TOT * DIM];  // [B*L, DIM]

// ---------------------------------------------------------------------------
// Tiled fp32 GEMM with bias:  C[M,N] = A[M,K] @ W[K,N] + bias[N]
// BM=BN=128, BK=16, 256 threads, 8x8 register tile per thread.
// Requires M%128==0, N%128==0, K%16==0 (true for all shapes here).
// ---------------------------------------------------------------------------
__global__ __launch_bounds__(256) void gemm_bias(
    const float* __restrict__ A, const float* __restrict__ W,
    const float* __restrict__ bias, float* __restrict__ C,
    int M, int N, int K)
{
    __shared__ float As[16][132];   // transposed A tile: As[k][m]
    __shared__ float Bs[16][132];   // Bs[k][n]

    const int tid = threadIdx.x;
    const int tx  = tid & 15;       // 0..15 -> 8 output cols each
    const int ty  = tid >> 4;       // 0..15 -> 8 output rows each
    const int mBase = blockIdx.y * 128;
    const int nBase = blockIdx.x * 128;

    float acc[8][8];
#pragma unroll
    for (int i = 0; i < 8; ++i)
#pragma unroll
        for (int j = 0; j < 8; ++j) acc[i][j] = 0.0f;

    for (int k0 = 0; k0 < K; k0 += 16) {
        // Load A tile 128x16 (512 float4, 2 per thread), store transposed
#pragma unroll
        for (int it = 0; it < 2; ++it) {
            int idx = tid + it * 256;          // float4 index
            int row = idx >> 2;                // 4 float4 per row of 16
            int k4  = (idx & 3) * 4;
            float4 v = *(const float4*)&A[(size_t)(mBase + row) * K + k0 + k4];
            As[k4 + 0][row] = v.x;
            As[k4 + 1][row] = v.y;
            As[k4 + 2][row] = v.z;
            As[k4 + 3][row] = v.w;
        }
        // Load W tile 16x128 (512 float4, 2 per thread)
#pragma unroll
        for (int it = 0; it < 2; ++it) {
            int idx = tid + it * 256;
            int row = idx >> 5;                // 32 float4 per row of 128
            int c4  = (idx & 31) * 4;
            float4 v = *(const float4*)&W[(size_t)(k0 + row) * N + nBase + c4];
            *(float4*)&Bs[row][c4] = v;
        }
        __syncthreads();

#pragma unroll
        for (int kk = 0; kk < 16; ++kk) {
            float a[8], b[8];
            *(float4*)&a[0] = *(const float4*)&As[kk][ty * 8];
            *(float4*)&a[4] = *(const float4*)&As[kk][ty * 8 + 4];
            *(float4*)&b[0] = *(const float4*)&Bs[kk][tx * 8];
            *(float4*)&b[4] = *(const float4*)&Bs[kk][tx * 8 + 4];
#pragma unroll
            for (int i = 0; i < 8; ++i)
#pragma unroll
                for (int j = 0; j < 8; ++j)
                    acc[i][j] += a[i] * b[j];
        }
        __syncthreads();
    }

    // Epilogue: add bias, vectorized stores
#pragma unroll
    for (int i = 0; i < 8; ++i) {
        int m = mBase + ty * 8 + i;
#pragma unroll
        for (int j = 0; j < 8; j += 4) {
            int n = nBase + tx * 8 + j;
            float4 bv = *(const float4*)&bias[n];
            float4 o;
            o.x = acc[i][j + 0] + bv.x;
            o.y = acc[i][j + 1] + bv.y;
            o.z = acc[i][j + 2] + bv.z;
            o.w = acc[i][j + 3] + bv.w;
            *(float4*)&C[(size_t)m * N + n] = o;
        }
    }
}

// ---------------------------------------------------------------------------
// Causal flash attention, fp32.
// Grid: (SEQ/64, NH, B). Block: 256 threads.
// Each block: one 64-row Q tile of one (b,h). Streams 64-row K/V tiles.
// Thread (ty,tx): 4 q-rows (ty*4+i) x 4 cols/dims (tx*4+j).
// P is written transposed into the K smem buffer for the PV pass.
// ---------------------------------------------------------------------------
#define SPITCH 68   // smem row pitch (64 + 4 pad, keeps float4 alignment)

__global__ __launch_bounds__(256) void attn_fwd(
    const float* __restrict__ qkv, float* __restrict__ att)
{
    extern __shared__ float sm[];
    float (*Qs)[SPITCH] = (float(*)[SPITCH])sm;
    float (*Ks)[SPITCH] = (float(*)[SPITCH])(sm + 64 * SPITCH);      // also holds P^T
    float (*Vs)[SPITCH] = (float(*)[SPITCH])(sm + 2 * 64 * SPITCH);

    const int qt = blockIdx.x;
    const int h  = blockIdx.y;
    const int b  = blockIdx.z;
    const int tid = threadIdx.x;
    const int tx = tid & 15;
    const int ty = tid >> 4;
    const float scale = 0.125f;  // 1/sqrt(64)

    // Load + pre-scale Q tile (64x64)
    const float* qbase = qkv + ((size_t)(b * SEQ + qt * 64)) * D3 + h * HD;
#pragma unroll
    for (int it = 0; it < 4; ++it) {
        int i = tid + it * 256;            // float4 index, 1024 total
        int r  = i >> 4;
        int d4 = (i & 15) * 4;
        float4 v = *(const float4*)(qbase + (size_t)r * D3 + d4);
        float4 s; s.x = v.x * scale; s.y = v.y * scale; s.z = v.z * scale; s.w = v.w * scale;
        *(float4*)&Qs[r][d4] = s;
    }

    float m_i[4], l_i[4], O[4][4];
#pragma unroll
    for (int i = 0; i < 4; ++i) {
        m_i[i] = -INFINITY; l_i[i] = 0.0f;
#pragma unroll
        for (int j = 0; j < 4; ++j) O[i][j] = 0.0f;
    }

    for (int kt = 0; kt <= qt; ++kt) {
        // Load K and V tiles
        const float* kbase = qkv + ((size_t)(b * SEQ + kt * 64)) * D3 + DIM + h * HD;
        const float* vbase = kbase + DIM;
#pragma unroll
        for (int it = 0; it < 4; ++it) {
            int i = tid + it * 256;
            int r  = i >> 4;
            int d4 = (i & 15) * 4;
            *(float4*)&Ks[r][d4] = *(const float4*)(kbase + (size_t)r * D3 + d4);
            *(float4*)&Vs[r][d4] = *(const float4*)(vbase + (size_t)r * D3 + d4);
        }
        __syncthreads();

        // S = Q K^T  (4x4 per thread)
        float s[4][4];
#pragma unroll
        for (int i = 0; i < 4; ++i)
#pragma unroll
            for (int j = 0; j < 4; ++j) s[i][j] = 0.0f;

#pragma unroll
        for (int d4 = 0; d4 < 64; d4 += 4) {
            float4 q[4], k[4];
#pragma unroll
            for (int i = 0; i < 4; ++i) q[i] = *(const float4*)&Qs[ty * 4 + i][d4];
#pragma unroll
            for (int j = 0; j < 4; ++j) k[j] = *(const float4*)&Ks[tx * 4 + j][d4];
#pragma unroll
            for (int i = 0; i < 4; ++i)
#pragma unroll
                for (int j = 0; j < 4; ++j)
                    s[i][j] += q[i].x * k[j].x + q[i].y * k[j].y
                             + q[i].z * k[j].z + q[i].w * k[j].w;
        }

        // Causal mask on the diagonal tile
        if (kt == qt) {
#pragma unroll
            for (int i = 0; i < 4; ++i)
#pragma unroll
                for (int j = 0; j < 4; ++j)
                    if (tx * 4 + j > ty * 4 + i) s[i][j] = -1e30f;
        }

        // Online softmax update (row stats shared by the 16 tx lanes, width-16 shfl)
#pragma unroll
        for (int i = 0; i < 4; ++i) {
            float tm = fmaxf(fmaxf(s[i][0], s[i][1]), fmaxf(s[i][2], s[i][3]));
#pragma unroll
            for (int off = 8; off >= 1; off >>= 1)
                tm = fmaxf(tm, __shfl_xor_sync(0xffffffffu, tm, off, 16));
            float m_new = fmaxf(m_i[i], tm);
            float alpha = __expf(m_i[i] - m_new);
            float rs = 0.0f;
#pragma unroll
            for (int j = 0; j < 4; ++j) {
                s[i][j] = __expf(s[i][j] - m_new);
                rs += s[i][j];
            }
#pragma unroll
            for (int off = 8; off >= 1; off >>= 1)
                rs += __shfl_xor_sync(0xffffffffu, rs, off, 16);
            l_i[i] = l_i[i] * alpha + rs;
            m_i[i] = m_new;
#pragma unroll
            for (int j = 0; j < 4; ++j) O[i][j] *= alpha;
        }

        // Store P transposed into the K buffer: Pt[c][r]
        __syncthreads();
#pragma unroll
        for (int i = 0; i < 4; ++i)
#pragma unroll
            for (int j = 0; j < 4; ++j)
                Ks[tx * 4 + j][ty * 4 + i] = s[i][j];
        __syncthreads();

        // O += P @ V  (2x LDS.128 per 16 FMA per key)
#pragma unroll 4
        for (int c = 0; c < 64; ++c) {
            float4 p4 = *(const float4*)&Ks[c][ty * 4];   // rows i
            float4 v4 = *(const float4*)&Vs[c][tx * 4];   // dims j
            O[0][0] += p4.x * v4.x; O[0][1] += p4.x * v4.y; O[0][2] += p4.x * v4.z; O[0][3] += p4.x * v4.w;
            O[1][0] += p4.y * v4.x; O[1][1] += p4.y * v4.y; O[1][2] += p4.y * v4.z; O[1][3] += p4.y * v4.w;
            O[2][0] += p4.z * v4.x; O[2][1] += p4.z * v4.y; O[2][2] += p4.z * v4.z; O[2][3] += p4.z * v4.w;
            O[3][0] += p4.w * v4.x; O[3][1] += p4.w * v4.y; O[3][2] += p4.w * v4.z; O[3][3] += p4.w * v4.w;
        }
        __syncthreads();  // protect Ks/Vs before next tile load
    }

    // Normalize and write out (layout [B,L,H,d] == [B*L, DIM])
    float* obase = att + ((size_t)(b * SEQ + qt * 64)) * DIM + h * HD;
#pragma unroll
    for (int i = 0; i < 4; ++i) {
        float inv = 1.0f / l_i[i];
        float4 o;
        o.x = O[i][0] * inv; o.y = O[i][1] * inv;
        o.z = O[i][2] * inv; o.w = O[i][3] * inv;
        *(float4*)(obase + (size_t)(ty * 4 + i) * DIM + tx * 4) = o;
    }
}

// ---------------------------------------------------------------------------
extern "C" void kernel_launch(void* const* d_in, const int* in_sizes, int n_in,
                              void* d_out, int out_size)
{
    const float* x     = (const float*)d_in[0];
    const float* w_qkv = (const float*)d_in[1];
    const float* b_qkv = (const float*)d_in[2];
    const float* w_out = (const float*)d_in[3];
    const float* b_out = (const float*)d_in[4];
    float* out = (float*)d_out;

    float *qkv_ptr, *att_ptr;
    cudaGetSymbolAddress((void**)&qkv_ptr, g_qkv);
    cudaGetSymbolAddress((void**)&att_ptr, g_att);

    // 1) QKV projection: [8192,1024] x [1024,3072] + bias
    gemm_bias<<<dim3(D3 / 128, M_TOT / 128), 256>>>(
        x, w_qkv, b_qkv, qkv_ptr, M_TOT, D3, DIM);

    // 2) Causal flash attention
    const int smem = 3 * 64 * SPITCH * (int)sizeof(float);  // 52224 B
    cudaFuncSetAttribute(attn_fwd, cudaFuncAttributeMaxDynamicSharedMemorySize, smem);
    attn_fwd<<<dim3(SEQ / 64, NH, B_SZ), 256, smem>>>(qkv_ptr, att_ptr);

    // 3) Output projection: [8192,1024] x [1024,1024] + bias
    gemm_bias<<<dim3(DIM / 128, M_TOT / 128), 256>>>(
        att_ptr, w_out, b_out, out, M_TOT, DIM, DIM);
}

// round 2
// speedup vs baseline: 1.2674x; 1.2674x over previous
#include <cuda_runtime.h>
#include <math.h>
#include <stdint.h>

#define B_SZ 4
#define SEQ  2048
#define DIM  1024
#define NH   16
#define HD   64
#define D3   3072
#define M_TOT (B_SZ * SEQ)

// Scratch (device globals — no runtime allocation allowed)
__device__ float g_qkv[(size_t)M_TOT * D3];   // [B*L, 3*DIM]
__device__ float g_att[(size_t)M_TOT * DIM];  // [B*L, DIM]

// ---------------------------------------------------------------------------
// tf32 tensor-core GEMM with bias:  C[M,N] = A[M,K] @ W[K,N] + bias[N]
// BM=BN=128, BK=32, 256 threads (8 warps, 2x4), warp tile 64x32,
// mma.sync.m16n8k8.tf32, register-double-buffered global->smem pipeline.
// Requires M%128==0, N%128==0, K%32==0.
// ---------------------------------------------------------------------------
#define GP 136   // smem pitch: 136 mod 32 = 8 -> fragment reads conflict-free

__device__ __forceinline__ uint32_t f2tf32(float f) {
    uint32_t r;
    asm("cvt.rna.tf32.f32 %0, %1;" : "=r"(r) : "f"(f));
    return r;
}

__device__ __forceinline__ void mma_tf32(float c[4], const uint32_t a[4], const uint32_t b[2]) {
    asm volatile(
        "mma.sync.aligned.m16n8k8.row.col.f32.tf32.tf32.f32 "
        "{%0,%1,%2,%3}, {%4,%5,%6,%7}, {%8,%9}, {%0,%1,%2,%3};"
        : "+f"(c[0]), "+f"(c[1]), "+f"(c[2]), "+f"(c[3])
        : "r"(a[0]), "r"(a[1]), "r"(a[2]), "r"(a[3]), "r"(b[0]), "r"(b[1]));
}

__global__ __launch_bounds__(256) void gemm_bias_tc(
    const float* __restrict__ A, const float* __restrict__ W,
    const float* __restrict__ bias, float* __restrict__ C,
    int M, int N, int K)
{
    __shared__ float As[32][GP];   // k-major: As[k][m]
    __shared__ float Bs[32][GP];   // k-major: Bs[k][n]

    const int tid  = threadIdx.x;
    const int lane = tid & 31;
    const int warp = tid >> 5;
    const int warpM = warp >> 2;      // 0..1  -> 64 rows each
    const int warpN = warp & 3;       // 0..3  -> 32 cols each
    const int g  = lane >> 2;         // 0..7
    const int t4 = lane & 3;          // 0..3
    const int mBase = blockIdx.y * 128;
    const int nBase = blockIdx.x * 128;

    // per-thread load coordinates (float4 granularity)
    // A tile: 128 rows x 32 k  = 1024 float4, 4 per thread
    // B tile: 32 rows  x 128 n = 1024 float4, 4 per thread
    int aRow[4], aK4[4], bRow[4], bC4[4];
#pragma unroll
    for (int f = 0; f < 4; ++f) {
        int idx = tid + f * 256;
        aRow[f] = idx >> 3;  aK4[f] = (idx & 7) * 4;
        bRow[f] = idx >> 5;  bC4[f] = (idx & 31) * 4;
    }

    float acc[4][4][4];
#pragma unroll
    for (int mi = 0; mi < 4; ++mi)
#pragma unroll
        for (int ni = 0; ni < 4; ++ni)
#pragma unroll
            for (int r = 0; r < 4; ++r) acc[mi][ni][r] = 0.0f;

    float4 pa[4], pb[4];

    // prologue: load tile k0=0
#pragma unroll
    for (int f = 0; f < 4; ++f) {
        pa[f] = *(const float4*)&A[(size_t)(mBase + aRow[f]) * K + aK4[f]];
        pb[f] = *(const float4*)&W[(size_t)bRow[f] * N + nBase + bC4[f]];
    }
#pragma unroll
    for (int f = 0; f < 4; ++f) {
        As[aK4[f] + 0][aRow[f]] = pa[f].x;
        As[aK4[f] + 1][aRow[f]] = pa[f].y;
        As[aK4[f] + 2][aRow[f]] = pa[f].z;
        As[aK4[f] + 3][aRow[f]] = pa[f].w;
        *(float4*)&Bs[bRow[f]][bC4[f]] = pb[f];
    }
    __syncthreads();

    for (int k0 = 0; k0 < K; k0 += 32) {
        const bool hasNext = (k0 + 32) < K;
        if (hasNext) {
#pragma unroll
            for (int f = 0; f < 4; ++f) {
                pa[f] = *(const float4*)&A[(size_t)(mBase + aRow[f]) * K + k0 + 32 + aK4[f]];
                pb[f] = *(const float4*)&W[(size_t)(k0 + 32 + bRow[f]) * N + nBase + bC4[f]];
            }
        }

        // compute: 4 k-fragments of 8
#pragma unroll
        for (int kb = 0; kb < 32; kb += 8) {
            uint32_t afr[4][4], bfr[4][2];
#pragma unroll
            for (int mi = 0; mi < 4; ++mi) {
                int m = warpM * 64 + mi * 16;
                afr[mi][0] = f2tf32(As[kb + t4    ][m + g    ]);
                afr[mi][1] = f2tf32(As[kb + t4    ][m + g + 8]);
                afr[mi][2] = f2tf32(As[kb + t4 + 4][m + g    ]);
                afr[mi][3] = f2tf32(As[kb + t4 + 4][m + g + 8]);
            }
#pragma unroll
            for (int ni = 0; ni < 4; ++ni) {
                int n = warpN * 32 + ni * 8;
                bfr[ni][0] = f2tf32(Bs[kb + t4    ][n + g]);
                bfr[ni][1] = f2tf32(Bs[kb + t4 + 4][n + g]);
            }
#pragma unroll
            for (int mi = 0; mi < 4; ++mi)
#pragma unroll
                for (int ni = 0; ni < 4; ++ni)
                    mma_tf32(acc[mi][ni], afr[mi], bfr[ni]);
        }
        __syncthreads();

        if (hasNext) {
#pragma unroll
            for (int f = 0; f < 4; ++f) {
                As[aK4[f] + 0][aRow[f]] = pa[f].x;
                As[aK4[f] + 1][aRow[f]] = pa[f].y;
                As[aK4[f] + 2][aRow[f]] = pa[f].z;
                As[aK4[f] + 3][aRow[f]] = pa[f].w;
                *(float4*)&Bs[bRow[f]][bC4[f]] = pb[f];
            }
            __syncthreads();
        }
    }

    // epilogue: bias + float2 stores
#pragma unroll
    for (int mi = 0; mi < 4; ++mi) {
        int row0 = mBase + warpM * 64 + mi * 16 + g;
#pragma unroll
        for (int ni = 0; ni < 4; ++ni) {
            int col = nBase + warpN * 32 + ni * 8 + t4 * 2;
            float2 bv = *(const float2*)&bias[col];
            float2 o0, o1;
            o0.x = acc[mi][ni][0] + bv.x;
            o0.y = acc[mi][ni][1] + bv.y;
            o1.x = acc[mi][ni][2] + bv.x;
            o1.y = acc[mi][ni][3] + bv.y;
            *(float2*)&C[(size_t)row0 * N + col]       = o0;
            *(float2*)&C[(size_t)(row0 + 8) * N + col] = o1;
        }
    }
}

// ---------------------------------------------------------------------------
// Causal flash attention, fp32 (unchanged from round 1).
// ---------------------------------------------------------------------------
#define SPITCH 68

__global__ __launch_bounds__(256) void attn_fwd(
    const float* __restrict__ qkv, float* __restrict__ att)
{
    extern __shared__ float sm[];
    float (*Qs)[SPITCH] = (float(*)[SPITCH])sm;
    float (*Ks)[SPITCH] = (float(*)[SPITCH])(sm + 64 * SPITCH);
    float (*Vs)[SPITCH] = (float(*)[SPITCH])(sm + 2 * 64 * SPITCH);

    const int qt = blockIdx.x;
    const int h  = blockIdx.y;
    const int b  = blockIdx.z;
    const int tid = threadIdx.x;
    const int tx = tid & 15;
    const int ty = tid >> 4;
    const float scale = 0.125f;

    const float* qbase = qkv + ((size_t)(b * SEQ + qt * 64)) * D3 + h * HD;
#pragma unroll
    for (int it = 0; it < 4; ++it) {
        int i = tid + it * 256;
        int r  = i >> 4;
        int d4 = (i & 15) * 4;
        float4 v = *(const float4*)(qbase + (size_t)r * D3 + d4);
        float4 s; s.x = v.x * scale; s.y = v.y * scale; s.z = v.z * scale; s.w = v.w * scale;
        *(float4*)&Qs[r][d4] = s;
    }

    float m_i[4], l_i[4], O[4][4];
#pragma unroll
    for (int i = 0; i < 4; ++i) {
        m_i[i] = -INFINITY; l_i[i] = 0.0f;
#pragma unroll
        for (int j = 0; j < 4; ++j) O[i][j] = 0.0f;
    }

    for (int kt = 0; kt <= qt; ++kt) {
        const float* kbase = qkv + ((size_t)(b * SEQ + kt * 64)) * D3 + DIM + h * HD;
        const float* vbase = kbase + DIM;
#pragma unroll
        for (int it = 0; it < 4; ++it) {
            int i = tid + it * 256;
            int r  = i >> 4;
            int d4 = (i & 15) * 4;
            *(float4*)&Ks[r][d4] = *(const float4*)(kbase + (size_t)r * D3 + d4);
            *(float4*)&Vs[r][d4] = *(const float4*)(vbase + (size_t)r * D3 + d4);
        }
        __syncthreads();

        float s[4][4];
#pragma unroll
        for (int i = 0; i < 4; ++i)
#pragma unroll
            for (int j = 0; j < 4; ++j) s[i][j] = 0.0f;

#pragma unroll
        for (int d4 = 0; d4 < 64; d4 += 4) {
            float4 q[4], k[4];
#pragma unroll
            for (int i = 0; i < 4; ++i) q[i] = *(const float4*)&Qs[ty * 4 + i][d4];
#pragma unroll
            for (int j = 0; j < 4; ++j) k[j] = *(const float4*)&Ks[tx * 4 + j][d4];
#pragma unroll
            for (int i = 0; i < 4; ++i)
#pragma unroll
                for (int j = 0; j < 4; ++j)
                    s[i][j] += q[i].x * k[j].x + q[i].y * k[j].y
                             + q[i].z * k[j].z + q[i].w * k[j].w;
        }

        if (kt == qt) {
#pragma unroll
            for (int i = 0; i < 4; ++i)
#pragma unroll
                for (int j = 0; j < 4; ++j)
                    if (tx * 4 + j > ty * 4 + i) s[i][j] = -1e30f;
        }

#pragma unroll
        for (int i = 0; i < 4; ++i) {
            float tm = fmaxf(fmaxf(s[i][0], s[i][1]), fmaxf(s[i][2], s[i][3]));
#pragma unroll
            for (int off = 8; off >= 1; off >>= 1)
                tm = fmaxf(tm, __shfl_xor_sync(0xffffffffu, tm, off, 16));
            float m_new = fmaxf(m_i[i], tm);
            float alpha = __expf(m_i[i] - m_new);
            float rs = 0.0f;
#pragma unroll
            for (int j = 0; j < 4; ++j) {
                s[i][j] = __expf(s[i][j] - m_new);
                rs += s[i][j];
            }
#pragma unroll
            for (int off = 8; off >= 1; off >>= 1)
                rs += __shfl_xor_sync(0xffffffffu, rs, off, 16);
            l_i[i] = l_i[i] * alpha + rs;
            m_i[i] = m_new;
#pragma unroll
            for (int j = 0; j < 4; ++j) O[i][j] *= alpha;
        }

        __syncthreads();
#pragma unroll
        for (int i = 0; i < 4; ++i)
#pragma unroll
            for (int j = 0; j < 4; ++j)
                Ks[tx * 4 + j][ty * 4 + i] = s[i][j];
        __syncthreads();

#pragma unroll 4
        for (int c = 0; c < 64; ++c) {
            float4 p4 = *(const float4*)&Ks[c][ty * 4];
            float4 v4 = *(const float4*)&Vs[c][tx * 4];
            O[0][0] += p4.x * v4.x; O[0][1] += p4.x * v4.y; O[0][2] += p4.x * v4.z; O[0][3] += p4.x * v4.w;
            O[1][0] += p4.y * v4.x; O[1][1] += p4.y * v4.y; O[1][2] += p4.y * v4.z; O[1][3] += p4.y * v4.w;
            O[2][0] += p4.z * v4.x; O[2][1] += p4.z * v4.y; O[2][2] += p4.z * v4.z; O[2][3] += p4.z * v4.w;
            O[3][0] += p4.w * v4.x; O[3][1] += p4.w * v4.y; O[3][2] += p4.w * v4.z; O[3][3] += p4.w * v4.w;
        }
        __syncthreads();
    }

    float* obase = att + ((size_t)(b * SEQ + qt * 64)) * DIM + h * HD;
#pragma unroll
    for (int i = 0; i < 4; ++i) {
        float inv = 1.0f / l_i[i];
        float4 o;
        o.x = O[i][0] * inv; o.y = O[i][1] * inv;
        o.z = O[i][2] * inv; o.w = O[i][3] * inv;
        *(float4*)(obase + (size_t)(ty * 4 + i) * DIM + tx * 4) = o;
    }
}

// ---------------------------------------------------------------------------
extern "C" void kernel_launch(void* const* d_in, const int* in_sizes, int n_in,
                              void* d_out, int out_size)
{
    const float* x     = (const float*)d_in[0];
    const float* w_qkv = (const float*)d_in[1];
    const float* b_qkv = (const float*)d_in[2];
    const float* w_out = (const float*)d_in[3];
    const float* b_out = (const float*)d_in[4];
    float* out = (float*)d_out;

    float *qkv_ptr, *att_ptr;
    cudaGetSymbolAddress((void**)&qkv_ptr, g_qkv);
    cudaGetSymbolAddress((void**)&att_ptr, g_att);

    // 1) QKV projection: [8192,1024] x [1024,3072] + bias  (tf32 tensor cores)
    gemm_bias_tc<<<dim3(D3 / 128, M_TOT / 128), 256>>>(
        x, w_qkv, b_qkv, qkv_ptr, M_TOT, D3, DIM);

    // 2) Causal flash attention (fp32)
    const int smem = 3 * 64 * SPITCH * (int)sizeof(float);
    cudaFuncSetAttribute(attn_fwd, cudaFuncAttributeMaxDynamicSharedMemorySize, smem);
    attn_fwd<<<dim3(SEQ / 64, NH, B_SZ), 256, smem>>>(qkv_ptr, att_ptr);

    // 3) Output projection: [8192,1024] x [1024,1024] + bias  (tf32 tensor cores)
    gemm_bias_tc<<<dim3(DIM / 128, M_TOT / 128), 256>>>(
        att_ptr, w_out, b_out, out, M_TOT, DIM, DIM);
}

// round 3
// speedup vs baseline: 2.8179x; 2.2235x over previous
#include <cuda_runtime.h>
#include <math.h>
#include <stdint.h>

#define B_SZ 4
#define SEQ  2048
#define DIM  1024
#define NH   16
#define HD   64
#define D3   3072
#define M_TOT (B_SZ * SEQ)

__device__ float g_qkv[(size_t)M_TOT * D3];   // [B*L, 3*DIM]
__device__ float g_att[(size_t)M_TOT * DIM];  // [B*L, DIM]

// ---------------------------------------------------------------------------
// Common helpers
// ---------------------------------------------------------------------------
__device__ __forceinline__ uint32_t f2tf32(float f) {
    uint32_t r;
    asm("cvt.rna.tf32.f32 %0, %1;" : "=r"(r) : "f"(f));
    return r;
}
__device__ __forceinline__ float tf32f(float f) {   // tf32 bits stored in a float
    return __uint_as_float(f2tf32(f));
}
__device__ __forceinline__ void mma_tf32(float c[4], const uint32_t a[4], const uint32_t b[2]) {
    asm volatile(
        "mma.sync.aligned.m16n8k8.row.col.f32.tf32.tf32.f32 "
        "{%0,%1,%2,%3}, {%4,%5,%6,%7}, {%8,%9}, {%0,%1,%2,%3};"
        : "+f"(c[0]), "+f"(c[1]), "+f"(c[2]), "+f"(c[3])
        : "r"(a[0]), "r"(a[1]), "r"(a[2]), "r"(a[3]), "r"(b[0]), "r"(b[1]));
}

// ---------------------------------------------------------------------------
// tf32 tensor-core GEMM with bias. BM=BN=128, BK=32, 256 threads, 8 warps
// (2x4), warp tile 64x32. tf32 conversion happens at smem store -> the inner
// loop is pure LDS + MMA.
// ---------------------------------------------------------------------------
#define GP 136

__global__ __launch_bounds__(256) void gemm_bias_tc(
    const float* __restrict__ A, const float* __restrict__ W,
    const float* __restrict__ bias, float* __restrict__ C,
    int M, int N, int K)
{
    __shared__ float As[32][GP];   // k-major: As[k][m], tf32 bits
    __shared__ float Bs[32][GP];   // k-major: Bs[k][n], tf32 bits

    const int tid  = threadIdx.x;
    const int lane = tid & 31;
    const int warp = tid >> 5;
    const int warpM = warp >> 2;
    const int warpN = warp & 3;
    const int g  = lane >> 2;
    const int t4 = lane & 3;
    const int mBase = blockIdx.y * 128;
    const int nBase = blockIdx.x * 128;

    int aRow[4], aK4[4], bRow[4], bC4[4];
#pragma unroll
    for (int f = 0; f < 4; ++f) {
        int idx = tid + f * 256;
        aRow[f] = idx >> 3;  aK4[f] = (idx & 7) * 4;
        bRow[f] = idx >> 5;  bC4[f] = (idx & 31) * 4;
    }

    float acc[4][4][4];
#pragma unroll
    for (int mi = 0; mi < 4; ++mi)
#pragma unroll
        for (int ni = 0; ni < 4; ++ni)
#pragma unroll
            for (int r = 0; r < 4; ++r) acc[mi][ni][r] = 0.0f;

    float4 pa[4], pb[4];

#pragma unroll
    for (int f = 0; f < 4; ++f) {
        pa[f] = *(const float4*)&A[(size_t)(mBase + aRow[f]) * K + aK4[f]];
        pb[f] = *(const float4*)&W[(size_t)bRow[f] * N + nBase + bC4[f]];
    }
#pragma unroll
    for (int f = 0; f < 4; ++f) {
        As[aK4[f] + 0][aRow[f]] = tf32f(pa[f].x);
        As[aK4[f] + 1][aRow[f]] = tf32f(pa[f].y);
        As[aK4[f] + 2][aRow[f]] = tf32f(pa[f].z);
        As[aK4[f] + 3][aRow[f]] = tf32f(pa[f].w);
        Bs[bRow[f]][bC4[f] + 0] = tf32f(pb[f].x);
        Bs[bRow[f]][bC4[f] + 1] = tf32f(pb[f].y);
        Bs[bRow[f]][bC4[f] + 2] = tf32f(pb[f].z);
        Bs[bRow[f]][bC4[f] + 3] = tf32f(pb[f].w);
    }
    __syncthreads();

    for (int k0 = 0; k0 < K; k0 += 32) {
        const bool hasNext = (k0 + 32) < K;
        if (hasNext) {
#pragma unroll
            for (int f = 0; f < 4; ++f) {
                pa[f] = *(const float4*)&A[(size_t)(mBase + aRow[f]) * K + k0 + 32 + aK4[f]];
                pb[f] = *(const float4*)&W[(size_t)(k0 + 32 + bRow[f]) * N + nBase + bC4[f]];
            }
        }

#pragma unroll
        for (int kb = 0; kb < 32; kb += 8) {
            uint32_t afr[4][4], bfr[4][2];
#pragma unroll
            for (int mi = 0; mi < 4; ++mi) {
                int m = warpM * 64 + mi * 16;
                afr[mi][0] = __float_as_uint(As[kb + t4    ][m + g    ]);
                afr[mi][1] = __float_as_uint(As[kb + t4    ][m + g + 8]);
                afr[mi][2] = __float_as_uint(As[kb + t4 + 4][m + g    ]);
                afr[mi][3] = __float_as_uint(As[kb + t4 + 4][m + g + 8]);
            }
#pragma unroll
            for (int ni = 0; ni < 4; ++ni) {
                int n = warpN * 32 + ni * 8;
                bfr[ni][0] = __float_as_uint(Bs[kb + t4    ][n + g]);
                bfr[ni][1] = __float_as_uint(Bs[kb + t4 + 4][n + g]);
            }
#pragma unroll
            for (int mi = 0; mi < 4; ++mi)
#pragma unroll
                for (int ni = 0; ni < 4; ++ni)
                    mma_tf32(acc[mi][ni], afr[mi], bfr[ni]);
        }
        __syncthreads();

        if (hasNext) {
#pragma unroll
            for (int f = 0; f < 4; ++f) {
                As[aK4[f] + 0][aRow[f]] = tf32f(pa[f].x);
                As[aK4[f] + 1][aRow[f]] = tf32f(pa[f].y);
                As[aK4[f] + 2][aRow[f]] = tf32f(pa[f].z);
                As[aK4[f] + 3][aRow[f]] = tf32f(pa[f].w);
                Bs[bRow[f]][bC4[f] + 0] = tf32f(pb[f].x);
                Bs[bRow[f]][bC4[f] + 1] = tf32f(pb[f].y);
                Bs[bRow[f]][bC4[f] + 2] = tf32f(pb[f].z);
                Bs[bRow[f]][bC4[f] + 3] = tf32f(pb[f].w);
            }
            __syncthreads();
        }
    }

#pragma unroll
    for (int mi = 0; mi < 4; ++mi) {
        int row0 = mBase + warpM * 64 + mi * 16 + g;
#pragma unroll
        for (int ni = 0; ni < 4; ++ni) {
            int col = nBase + warpN * 32 + ni * 8 + t4 * 2;
            float2 bv = *(const float2*)&bias[col];
            float2 o0, o1;
            o0.x = acc[mi][ni][0] + bv.x;
            o0.y = acc[mi][ni][1] + bv.y;
            o1.x = acc[mi][ni][2] + bv.x;
            o1.y = acc[mi][ni][3] + bv.y;
            *(float2*)&C[(size_t)row0 * N + col]       = o0;
            *(float2*)&C[(size_t)(row0 + 8) * N + col] = o1;
        }
    }
}

// ---------------------------------------------------------------------------
// Causal flash attention on tf32 tensor cores.
// CTA: 256 threads (8 warps). Q tile 128 rows; each warp owns 16 rows.
// K/V tiles of 64 keys. S and O via mma.sync m16n8k8; warp-local softmax.
// ---------------------------------------------------------------------------
#define AP 68   // pitch for Qs/Ks/Ps: [row][k] fragment reads -> bank 4g+t4
#define VP 72   // pitch for Vs:       [k][n]  fragment reads -> bank 8t4+g

__global__ __launch_bounds__(256) void attn_fwd_tc(
    const float* __restrict__ qkv, float* __restrict__ att)
{
    extern __shared__ float sm[];
    float (*Qs)[AP] = (float(*)[AP])sm;                          // [128][68]
    float (*Ks)[AP] = (float(*)[AP])(sm + 128 * AP);             // [64][68]
    float (*Vs)[VP] = (float(*)[VP])(sm + 128 * AP + 64 * AP);   // [64][72]
    float (*Ps)[AP] = (float(*)[AP])(sm + 128 * AP + 64 * AP + 64 * VP); // [128][68]

    const int qt = blockIdx.x;
    const int h  = blockIdx.y;
    const int b  = blockIdx.z;
    const int qBase = qt * 128;
    const int tid  = threadIdx.x;
    const int lane = tid & 31;
    const int warp = tid >> 5;
    const int g  = lane >> 2;
    const int t4 = lane & 3;
    const int wrow = warp * 16;
    const float scale = 0.125f;

    // Load + scale + tf32-convert Q tile (128x64)
    const float* qb = qkv + ((size_t)(b * SEQ + qBase)) * D3 + h * HD;
#pragma unroll
    for (int it = 0; it < 8; ++it) {
        int i = tid + it * 256;
        int r  = i >> 4;
        int c4 = (i & 15) * 4;
        float4 v = *(const float4*)(qb + (size_t)r * D3 + c4);
        Qs[r][c4 + 0] = tf32f(v.x * scale);
        Qs[r][c4 + 1] = tf32f(v.y * scale);
        Qs[r][c4 + 2] = tf32f(v.z * scale);
        Qs[r][c4 + 3] = tf32f(v.w * scale);
    }

    float m_i[2] = {-INFINITY, -INFINITY};
    float l_i[2] = {0.0f, 0.0f};
    float O[8][4];
#pragma unroll
    for (int ni = 0; ni < 8; ++ni)
#pragma unroll
        for (int r = 0; r < 4; ++r) O[ni][r] = 0.0f;

    const int nkt = qBase / 64 + 2;   // last two tiles need masking

    for (int kt = 0; kt < nkt; ++kt) {
        const int ktBase = kt * 64;
        // Load K and V tiles (64x64 each), tf32-convert
        const float* kb = qkv + ((size_t)(b * SEQ + ktBase)) * D3 + DIM + h * HD;
#pragma unroll
        for (int it = 0; it < 4; ++it) {
            int i = tid + it * 256;
            int r  = i >> 4;
            int c4 = (i & 15) * 4;
            float4 kv = *(const float4*)(kb + (size_t)r * D3 + c4);
            Ks[r][c4 + 0] = tf32f(kv.x);
            Ks[r][c4 + 1] = tf32f(kv.y);
            Ks[r][c4 + 2] = tf32f(kv.z);
            Ks[r][c4 + 3] = tf32f(kv.w);
            float4 vv = *(const float4*)(kb + DIM + (size_t)r * D3 + c4);
            Vs[r][c4 + 0] = tf32f(vv.x);
            Vs[r][c4 + 1] = tf32f(vv.y);
            Vs[r][c4 + 2] = tf32f(vv.z);
            Vs[r][c4 + 3] = tf32f(vv.w);
        }
        __syncthreads();

        // S[16x64] per warp = Q_warp[16x64] . K^T
        float sc[8][4];
#pragma unroll
        for (int ni = 0; ni < 8; ++ni)
#pragma unroll
            for (int r = 0; r < 4; ++r) sc[ni][r] = 0.0f;

#pragma unroll
        for (int kb8 = 0; kb8 < 64; kb8 += 8) {
            uint32_t a[4];
            a[0] = __float_as_uint(Qs[wrow + g    ][kb8 + t4    ]);
            a[1] = __float_as_uint(Qs[wrow + g + 8][kb8 + t4    ]);
            a[2] = __float_as_uint(Qs[wrow + g    ][kb8 + t4 + 4]);
            a[3] = __float_as_uint(Qs[wrow + g + 8][kb8 + t4 + 4]);
#pragma unroll
            for (int ni = 0; ni < 8; ++ni) {
                uint32_t bb[2];
                bb[0] = __float_as_uint(Ks[ni * 8 + g][kb8 + t4    ]);
                bb[1] = __float_as_uint(Ks[ni * 8 + g][kb8 + t4 + 4]);
                mma_tf32(sc[ni], a, bb);
            }
        }

        // Causal mask (only last two tiles can hit it)
        if (ktBase + 63 > qBase + wrow) {
            const int r0 = qBase + wrow + g;
            const int r1 = r0 + 8;
#pragma unroll
            for (int ni = 0; ni < 8; ++ni) {
                int c0 = ktBase + ni * 8 + t4 * 2;
                int c1 = c0 + 1;
                if (c0 > r0) sc[ni][0] = -1e30f;
                if (c1 > r0) sc[ni][1] = -1e30f;
                if (c0 > r1) sc[ni][2] = -1e30f;
                if (c1 > r1) sc[ni][3] = -1e30f;
            }
        }

        // Online softmax: rows g (regs 0,1) and g+8 (regs 2,3); quad-reduce.
#pragma unroll
        for (int hrow = 0; hrow < 2; ++hrow) {
            const int i0 = hrow * 2, i1 = hrow * 2 + 1;
            float tm = -INFINITY;
#pragma unroll
            for (int ni = 0; ni < 8; ++ni)
                tm = fmaxf(tm, fmaxf(sc[ni][i0], sc[ni][i1]));
            tm = fmaxf(tm, __shfl_xor_sync(0xffffffffu, tm, 1, 4));
            tm = fmaxf(tm, __shfl_xor_sync(0xffffffffu, tm, 2, 4));
            float m_new = fmaxf(m_i[hrow], tm);
            float alpha = __expf(m_i[hrow] - m_new);
            float rs = 0.0f;
#pragma unroll
            for (int ni = 0; ni < 8; ++ni) {
                sc[ni][i0] = __expf(sc[ni][i0] - m_new);
                sc[ni][i1] = __expf(sc[ni][i1] - m_new);
                rs += sc[ni][i0] + sc[ni][i1];
            }
            rs += __shfl_xor_sync(0xffffffffu, rs, 1, 4);
            rs += __shfl_xor_sync(0xffffffffu, rs, 2, 4);
            l_i[hrow] = l_i[hrow] * alpha + rs;
            m_i[hrow] = m_new;
#pragma unroll
            for (int ni = 0; ni < 8; ++ni) {
                O[ni][i0] *= alpha;
                O[ni][i1] *= alpha;
            }
        }

        // Write P (tf32) to smem for the PV mma
#pragma unroll
        for (int ni = 0; ni < 8; ++ni) {
            Ps[wrow + g    ][ni * 8 + t4 * 2    ] = tf32f(sc[ni][0]);
            Ps[wrow + g    ][ni * 8 + t4 * 2 + 1] = tf32f(sc[ni][1]);
            Ps[wrow + g + 8][ni * 8 + t4 * 2    ] = tf32f(sc[ni][2]);
            Ps[wrow + g + 8][ni * 8 + t4 * 2 + 1] = tf32f(sc[ni][3]);
        }
        __syncthreads();

        // O[16x64] += P[16x64] . V[64x64]
#pragma unroll
        for (int kb8 = 0; kb8 < 64; kb8 += 8) {
            uint32_t a[4];
            a[0] = __float_as_uint(Ps[wrow + g    ][kb8 + t4    ]);
            a[1] = __float_as_uint(Ps[wrow + g + 8][kb8 + t4    ]);
            a[2] = __float_as_uint(Ps[wrow + g    ][kb8 + t4 + 4]);
            a[3] = __float_as_uint(Ps[wrow + g + 8][kb8 + t4 + 4]);
#pragma unroll
            for (int ni = 0; ni < 8; ++ni) {
                uint32_t bb[2];
                bb[0] = __float_as_uint(Vs[kb8 + t4    ][ni * 8 + g]);
                bb[1] = __float_as_uint(Vs[kb8 + t4 + 4][ni * 8 + g]);
                mma_tf32(O[ni], a, bb);
            }
        }
        __syncthreads();   // protect Ks/Vs before next tile load
    }

    // Normalize + write out: att[b, qBase+row, h*64+col]
    float* ob = att + ((size_t)(b * SEQ + qBase + wrow)) * DIM + h * HD;
    const float inv0 = 1.0f / l_i[0];
    const float inv1 = 1.0f / l_i[1];
#pragma unroll
    for (int ni = 0; ni < 8; ++ni) {
        int col = ni * 8 + t4 * 2;
        float2 o0, o1;
        o0.x = O[ni][0] * inv0; o0.y = O[ni][1] * inv0;
        o1.x = O[ni][2] * inv1; o1.y = O[ni][3] * inv1;
        *(float2*)(ob + (size_t)(g    ) * DIM + col) = o0;
        *(float2*)(ob + (size_t)(g + 8) * DIM + col) = o1;
    }
}

// ---------------------------------------------------------------------------
extern "C" void kernel_launch(void* const* d_in, const int* in_sizes, int n_in,
                              void* d_out, int out_size)
{
    const float* x     = (const float*)d_in[0];
    const float* w_qkv = (const float*)d_in[1];
    const float* b_qkv = (const float*)d_in[2];
    const float* w_out = (const float*)d_in[3];
    const float* b_out = (const float*)d_in[4];
    float* out = (float*)d_out;

    float *qkv_ptr, *att_ptr;
    cudaGetSymbolAddress((void**)&qkv_ptr, g_qkv);
    cudaGetSymbolAddress((void**)&att_ptr, g_att);

    // 1) QKV projection (tf32 TC)
    gemm_bias_tc<<<dim3(D3 / 128, M_TOT / 128), 256>>>(
        x, w_qkv, b_qkv, qkv_ptr, M_TOT, D3, DIM);

    // 2) Causal flash attention (tf32 TC)
    const int smem = (128 * AP + 64 * AP + 64 * VP + 128 * AP) * (int)sizeof(float);
    cudaFuncSetAttribute(attn_fwd_tc, cudaFuncAttributeMaxDynamicSharedMemorySize, smem);
    attn_fwd_tc<<<dim3(SEQ / 128, NH, B_SZ), 256, smem>>>(qkv_ptr, att_ptr);

    // 3) Output projection (tf32 TC)
    gemm_bias_tc<<<dim3(DIM / 128, M_TOT / 128), 256>>>(
        att_ptr, w_out, b_out, out, M_TOT, DIM, DIM);
}

// round 4
// speedup vs baseline: 4.0273x; 1.4292x over previous
#include <cuda_runtime.h>
#include <math.h>
#include <stdint.h>

#define B_SZ 4
#define SEQ  2048
#define DIM  1024
#define NH   16
#define HD   64
#define D3   3072
#define M_TOT (B_SZ * SEQ)

// Scratch (device globals — no runtime allocation allowed)
__device__ float g_qkv[(size_t)M_TOT * D3];   // tf32-rounded qkv
__device__ float g_att[(size_t)M_TOT * DIM];  // tf32-rounded attention out
__device__ float g_x  [(size_t)M_TOT * DIM];  // tf32-rounded x
__device__ float g_w1 [(size_t)DIM * D3];     // tf32-rounded w_qkv
__device__ float g_w2 [(size_t)DIM * DIM];    // tf32-rounded w_out

// ---------------------------------------------------------------------------
// Helpers
// ---------------------------------------------------------------------------
__device__ __forceinline__ uint32_t f2tf32(float f) {
    uint32_t r;
    asm("cvt.rna.tf32.f32 %0, %1;" : "=r"(r) : "f"(f));
    return r;
}
__device__ __forceinline__ float tf32f(float f) {
    return __uint_as_float(f2tf32(f));
}
__device__ __forceinline__ void mma_tf32(float c[4], const uint32_t a[4], const uint32_t b[2]) {
    asm volatile(
        "mma.sync.aligned.m16n8k8.row.col.f32.tf32.tf32.f32 "
        "{%0,%1,%2,%3}, {%4,%5,%6,%7}, {%8,%9}, {%0,%1,%2,%3};"
        : "+f"(c[0]), "+f"(c[1]), "+f"(c[2]), "+f"(c[3])
        : "r"(a[0]), "r"(a[1]), "r"(a[2]), "r"(a[3]), "r"(b[0]), "r"(b[1]));
}
__device__ __forceinline__ void cpasync16(void* smem, const void* gmem) {
    uint32_t sa = (uint32_t)__cvta_generic_to_shared(smem);
    asm volatile("cp.async.cg.shared.global [%0], [%1], 16;" :: "r"(sa), "l"(gmem));
}
#define CP_COMMIT() asm volatile("cp.async.commit_group;" ::: "memory")
#define CP_WAIT(N)  asm volatile("cp.async.wait_group %0;" :: "n"(N) : "memory")

// ---------------------------------------------------------------------------
// Pre-round a float array to tf32 bits (vectorized).
// ---------------------------------------------------------------------------
__global__ __launch_bounds__(256) void round_tf32(
    const float* __restrict__ in, float* __restrict__ out, int n4)
{
    int i = blockIdx.x * blockDim.x + threadIdx.x;
    int stride = gridDim.x * blockDim.x;
    for (; i < n4; i += stride) {
        float4 v = ((const float4*)in)[i];
        float4 o;
        o.x = tf32f(v.x); o.y = tf32f(v.y); o.z = tf32f(v.z); o.w = tf32f(v.w);
        ((float4*)out)[i] = o;
    }
}

// ---------------------------------------------------------------------------
// tf32 TC GEMM with bias: C = A@W + bias. Inputs pre-rounded to tf32.
// BM=BN=128, BK=32, 256 thr, 8 warps (2x4), warp tile 64x32.
// cp.async 2-stage pipeline, A stored [m][k] (pitch 36), B [k][n] (pitch 136).
// ROUND_OUT: round outputs to tf32 (for intermediates feeding later tf32 mma).
// ---------------------------------------------------------------------------
#define AsP 36
#define BsP 136
#define GEMM_STAGE_A (128 * AsP)
#define GEMM_STAGE_B (32 * BsP)

template<int ROUND_OUT>
__global__ __launch_bounds__(256, 2) void gemm_bias_tc(
    const float* __restrict__ A, const float* __restrict__ W,
    const float* __restrict__ bias, float* __restrict__ C,
    int M, int N, int K)
{
    extern __shared__ float sm[];
    float* AsBase = sm;                       // [2][128][36]
    float* BsBase = sm + 2 * GEMM_STAGE_A;    // [2][32][136]

    const int tid  = threadIdx.x;
    const int lane = tid & 31;
    const int warp = tid >> 5;
    const int warpM = warp >> 2;
    const int warpN = warp & 3;
    const int g  = lane >> 2;
    const int t4 = lane & 3;
    const int mBase = blockIdx.y * 128;
    const int nBase = blockIdx.x * 128;

    // per-thread cp.async coordinates (16B granularity)
    int aRow[4], aC4[4], bRow[4], bC4[4];
#pragma unroll
    for (int f = 0; f < 4; ++f) {
        int idx = tid + f * 256;
        aRow[f] = idx >> 3;  aC4[f] = (idx & 7) * 4;     // A: 128 rows x 8 chunks
        bRow[f] = idx >> 5;  bC4[f] = (idx & 31) * 4;    // B: 32 rows x 32 chunks
    }

    float acc[4][4][4];
#pragma unroll
    for (int mi = 0; mi < 4; ++mi)
#pragma unroll
        for (int ni = 0; ni < 4; ++ni)
#pragma unroll
            for (int r = 0; r < 4; ++r) acc[mi][ni][r] = 0.0f;

    // prologue: stage 0 <- tile k0=0
    {
        float* As = AsBase; float* Bs = BsBase;
#pragma unroll
        for (int f = 0; f < 4; ++f) {
            cpasync16(&As[aRow[f] * AsP + aC4[f]], &A[(size_t)(mBase + aRow[f]) * K + aC4[f]]);
            cpasync16(&Bs[bRow[f] * BsP + bC4[f]], &W[(size_t)bRow[f] * N + nBase + bC4[f]]);
        }
        CP_COMMIT();
    }

    int stage = 0;
    for (int k0 = 0; k0 < K; k0 += 32) {
        const bool hasNext = (k0 + 32) < K;
        if (hasNext) {
            float* As = AsBase + (stage ^ 1) * GEMM_STAGE_A;
            float* Bs = BsBase + (stage ^ 1) * GEMM_STAGE_B;
#pragma unroll
            for (int f = 0; f < 4; ++f) {
                cpasync16(&As[aRow[f] * AsP + aC4[f]],
                          &A[(size_t)(mBase + aRow[f]) * K + k0 + 32 + aC4[f]]);
                cpasync16(&Bs[bRow[f] * BsP + bC4[f]],
                          &W[(size_t)(k0 + 32 + bRow[f]) * N + nBase + bC4[f]]);
            }
            CP_COMMIT();
            CP_WAIT(1);
        } else {
            CP_WAIT(0);
        }
        __syncthreads();

        const float* As = AsBase + stage * GEMM_STAGE_A;
        const float* Bs = BsBase + stage * GEMM_STAGE_B;
#pragma unroll
        for (int kb = 0; kb < 32; kb += 8) {
            uint32_t afr[4][4], bfr[4][2];
#pragma unroll
            for (int mi = 0; mi < 4; ++mi) {
                int m = warpM * 64 + mi * 16;
                afr[mi][0] = __float_as_uint(As[(m + g    ) * AsP + kb + t4    ]);
                afr[mi][1] = __float_as_uint(As[(m + g + 8) * AsP + kb + t4    ]);
                afr[mi][2] = __float_as_uint(As[(m + g    ) * AsP + kb + t4 + 4]);
                afr[mi][3] = __float_as_uint(As[(m + g + 8) * AsP + kb + t4 + 4]);
            }
#pragma unroll
            for (int ni = 0; ni < 4; ++ni) {
                int n = warpN * 32 + ni * 8;
                bfr[ni][0] = __float_as_uint(Bs[(kb + t4    ) * BsP + n + g]);
                bfr[ni][1] = __float_as_uint(Bs[(kb + t4 + 4) * BsP + n + g]);
            }
#pragma unroll
            for (int mi = 0; mi < 4; ++mi)
#pragma unroll
                for (int ni = 0; ni < 4; ++ni)
                    mma_tf32(acc[mi][ni], afr[mi], bfr[ni]);
        }
        __syncthreads();
        stage ^= 1;
    }

#pragma unroll
    for (int mi = 0; mi < 4; ++mi) {
        int row0 = mBase + warpM * 64 + mi * 16 + g;
#pragma unroll
        for (int ni = 0; ni < 4; ++ni) {
            int col = nBase + warpN * 32 + ni * 8 + t4 * 2;
            float2 bv = *(const float2*)&bias[col];
            float2 o0, o1;
            if (ROUND_OUT) {
                o0.x = tf32f(acc[mi][ni][0] + bv.x);
                o0.y = tf32f(acc[mi][ni][1] + bv.y);
                o1.x = tf32f(acc[mi][ni][2] + bv.x);
                o1.y = tf32f(acc[mi][ni][3] + bv.y);
            } else {
                o0.x = acc[mi][ni][0] + bv.x;
                o0.y = acc[mi][ni][1] + bv.y;
                o1.x = acc[mi][ni][2] + bv.x;
                o1.y = acc[mi][ni][3] + bv.y;
            }
            *(float2*)&C[(size_t)row0 * N + col]       = o0;
            *(float2*)&C[(size_t)(row0 + 8) * N + col] = o1;
        }
    }
}

// ---------------------------------------------------------------------------
// Causal flash attention, tf32 TC, cp.async double-buffered K/V.
// CTA: 256 thr (8 warps), Q tile 128 rows, K/V tiles 64 keys.
// qkv is pre-rounded to tf32 -> all loads are raw copies.
// ---------------------------------------------------------------------------
#define AQP 68   // Qs/Ps/Ks pitch: [row][k] reads -> bank 4g+t4
#define AVP 72   // Vs pitch:       [k][n] reads  -> bank 8t4+g
#define OFF_Q  0
#define OFF_P  (128 * AQP)
#define OFF_K  (OFF_P + 128 * AQP)          // [2][64][68]
#define OFF_V  (OFF_K + 2 * 64 * AQP)       // [2][64][72]
#define ATT_SMEM ((OFF_V + 2 * 64 * AVP) * 4)

__global__ __launch_bounds__(256) void attn_fwd_tc(
    const float* __restrict__ qkv, float* __restrict__ att)
{
    extern __shared__ float sm[];
    float* Qs = sm + OFF_Q;
    float* Ps = sm + OFF_P;

    const int qt = blockIdx.x;
    const int h  = blockIdx.y;
    const int b  = blockIdx.z;
    const int qBase = qt * 128;
    const int tid  = threadIdx.x;
    const int lane = tid & 31;
    const int warp = tid >> 5;
    const int g  = lane >> 2;
    const int t4 = lane & 3;
    const int wrow = warp * 16;
    const float scale = 0.125f;

    // Load + scale Q tile (values already tf32-rounded; x0.125 is exact)
    const float* qb = qkv + ((size_t)(b * SEQ + qBase)) * D3 + h * HD;
#pragma unroll
    for (int it = 0; it < 8; ++it) {
        int i = tid + it * 256;
        int r  = i >> 4;
        int c4 = (i & 15) * 4;
        float4 v = *(const float4*)(qb + (size_t)r * D3 + c4);
        float4 s; s.x = v.x * scale; s.y = v.y * scale; s.z = v.z * scale; s.w = v.w * scale;
        *(float4*)&Qs[r * AQP + c4] = s;
    }

    const int nkt = qBase / 64 + 2;
    const float* kvb = qkv + (size_t)(b * SEQ) * D3 + DIM + h * HD;

    // prologue: prefetch tile 0 into stage 0
    {
        float* Ks = sm + OFF_K;
        float* Vs = sm + OFF_V;
#pragma unroll
        for (int it = 0; it < 4; ++it) {
            int i = tid + it * 256;
            int r  = i >> 4;
            int c4 = (i & 15) * 4;
            cpasync16(&Ks[r * AQP + c4], kvb + (size_t)r * D3 + c4);
            cpasync16(&Vs[r * AVP + c4], kvb + DIM + (size_t)r * D3 + c4);
        }
        CP_COMMIT();
    }

    float m_i[2] = {-INFINITY, -INFINITY};
    float l_i[2] = {0.0f, 0.0f};
    float O[8][4];
#pragma unroll
    for (int ni = 0; ni < 8; ++ni)
#pragma unroll
        for (int r = 0; r < 4; ++r) O[ni][r] = 0.0f;

    for (int kt = 0; kt < nkt; ++kt) {
        const int stg = kt & 1;
        const bool hasNext = (kt + 1) < nkt;
        if (hasNext) {
            float* Kn = sm + OFF_K + (stg ^ 1) * 64 * AQP;
            float* Vn = sm + OFF_V + (stg ^ 1) * 64 * AVP;
            const float* src = kvb + (size_t)(kt + 1) * 64 * D3;
#pragma unroll
            for (int it = 0; it < 4; ++it) {
                int i = tid + it * 256;
                int r  = i >> 4;
                int c4 = (i & 15) * 4;
                cpasync16(&Kn[r * AQP + c4], src + (size_t)r * D3 + c4);
                cpasync16(&Vn[r * AVP + c4], src + DIM + (size_t)r * D3 + c4);
            }
            CP_COMMIT();
            CP_WAIT(1);
        } else {
            CP_WAIT(0);
        }
        __syncthreads();

        const float* Ks = sm + OFF_K + stg * 64 * AQP;
        const float* Vs = sm + OFF_V + stg * 64 * AVP;
        const int ktBase = kt * 64;

        // S[16x64] per warp
        float sc[8][4];
#pragma unroll
        for (int ni = 0; ni < 8; ++ni)
#pragma unroll
            for (int r = 0; r < 4; ++r) sc[ni][r] = 0.0f;

#pragma unroll
        for (int kb8 = 0; kb8 < 64; kb8 += 8) {
            uint32_t a[4];
            a[0] = __float_as_uint(Qs[(wrow + g    ) * AQP + kb8 + t4    ]);
            a[1] = __float_as_uint(Qs[(wrow + g + 8) * AQP + kb8 + t4    ]);
            a[2] = __float_as_uint(Qs[(wrow + g    ) * AQP + kb8 + t4 + 4]);
            a[3] = __float_as_uint(Qs[(wrow + g + 8) * AQP + kb8 + t4 + 4]);
#pragma unroll
            for (int ni = 0; ni < 8; ++ni) {
                uint32_t bb[2];
                bb[0] = __float_as_uint(Ks[(ni * 8 + g) * AQP + kb8 + t4    ]);
                bb[1] = __float_as_uint(Ks[(ni * 8 + g) * AQP + kb8 + t4 + 4]);
                mma_tf32(sc[ni], a, bb);
            }
        }

        // Causal mask
        if (ktBase + 63 > qBase + wrow) {
            const int r0 = qBase + wrow + g;
            const int r1 = r0 + 8;
#pragma unroll
            for (int ni = 0; ni < 8; ++ni) {
                int c0 = ktBase + ni * 8 + t4 * 2;
                int c1 = c0 + 1;
                if (c0 > r0) sc[ni][0] = -1e30f;
                if (c1 > r0) sc[ni][1] = -1e30f;
                if (c0 > r1) sc[ni][2] = -1e30f;
                if (c1 > r1) sc[ni][3] = -1e30f;
            }
        }

        // Online softmax (quad-reduce within 4 lanes of a row)
#pragma unroll
        for (int hrow = 0; hrow < 2; ++hrow) {
            const int i0 = hrow * 2, i1 = hrow * 2 + 1;
            float tm = -INFINITY;
#pragma unroll
            for (int ni = 0; ni < 8; ++ni)
                tm = fmaxf(tm, fmaxf(sc[ni][i0], sc[ni][i1]));
            tm = fmaxf(tm, __shfl_xor_sync(0xffffffffu, tm, 1, 4));
            tm = fmaxf(tm, __shfl_xor_sync(0xffffffffu, tm, 2, 4));
            float m_new = fmaxf(m_i[hrow], tm);
            float alpha = __expf(m_i[hrow] - m_new);
            float rs = 0.0f;
#pragma unroll
            for (int ni = 0; ni < 8; ++ni) {
                sc[ni][i0] = __expf(sc[ni][i0] - m_new);
                sc[ni][i1] = __expf(sc[ni][i1] - m_new);
                rs += sc[ni][i0] + sc[ni][i1];
            }
            rs += __shfl_xor_sync(0xffffffffu, rs, 1, 4);
            rs += __shfl_xor_sync(0xffffffffu, rs, 2, 4);
            l_i[hrow] = l_i[hrow] * alpha + rs;
            m_i[hrow] = m_new;
#pragma unroll
            for (int ni = 0; ni < 8; ++ni) {
                O[ni][i0] *= alpha;
                O[ni][i1] *= alpha;
            }
        }

        // P -> smem (tf32), warp-private rows
#pragma unroll
        for (int ni = 0; ni < 8; ++ni) {
            Ps[(wrow + g    ) * AQP + ni * 8 + t4 * 2    ] = tf32f(sc[ni][0]);
            Ps[(wrow + g    ) * AQP + ni * 8 + t4 * 2 + 1] = tf32f(sc[ni][1]);
            Ps[(wrow + g + 8) * AQP + ni * 8 + t4 * 2    ] = tf32f(sc[ni][2]);
            Ps[(wrow + g + 8) * AQP + ni * 8 + t4 * 2 + 1] = tf32f(sc[ni][3]);
        }
        __syncwarp();

        // O += P @ V
#pragma unroll
        for (int kb8 = 0; kb8 < 64; kb8 += 8) {
            uint32_t a[4];
            a[0] = __float_as_uint(Ps[(wrow + g    ) * AQP + kb8 + t4    ]);
            a[1] = __float_as_uint(Ps[(wrow + g + 8) * AQP + kb8 + t4    ]);
            a[2] = __float_as_uint(Ps[(wrow + g    ) * AQP + kb8 + t4 + 4]);
            a[3] = __float_as_uint(Ps[(wrow + g + 8) * AQP + kb8 + t4 + 4]);
#pragma unroll
            for (int ni = 0; ni < 8; ++ni) {
                uint32_t bb[2];
                bb[0] = __float_as_uint(Vs[(kb8 + t4    ) * AVP + ni * 8 + g]);
                bb[1] = __float_as_uint(Vs[(kb8 + t4 + 4) * AVP + ni * 8 + g]);
                mma_tf32(O[ni], a, bb);
            }
        }
        __syncthreads();  // all reads of stage done before it is overwritten
    }

    // Normalize + write out, rounded to tf32 (feeds the tf32 out-GEMM)
    float* ob = att + ((size_t)(b * SEQ + qBase + wrow)) * DIM + h * HD;
    const float inv0 = 1.0f / l_i[0];
    const float inv1 = 1.0f / l_i[1];
#pragma unroll
    for (int ni = 0; ni < 8; ++ni) {
        int col = ni * 8 + t4 * 2;
        float2 o0, o1;
        o0.x = tf32f(O[ni][0] * inv0); o0.y = tf32f(O[ni][1] * inv0);
        o1.x = tf32f(O[ni][2] * inv1); o1.y = tf32f(O[ni][3] * inv1);
        *(float2*)(ob + (size_t)(g    ) * DIM + col) = o0;
        *(float2*)(ob + (size_t)(g + 8) * DIM + col) = o1;
    }
}

// ---------------------------------------------------------------------------
extern "C" void kernel_launch(void* const* d_in, const int* in_sizes, int n_in,
                              void* d_out, int out_size)
{
    const float* x     = (const float*)d_in[0];
    const float* w_qkv = (const float*)d_in[1];
    const float* b_qkv = (const float*)d_in[2];
    const float* w_out = (const float*)d_in[3];
    const float* b_out = (const float*)d_in[4];
    float* out = (float*)d_out;

    float *qkv_p, *att_p, *x_p, *w1_p, *w2_p;
    cudaGetSymbolAddress((void**)&qkv_p, g_qkv);
    cudaGetSymbolAddress((void**)&att_p, g_att);
    cudaGetSymbolAddress((void**)&x_p,   g_x);
    cudaGetSymbolAddress((void**)&w1_p,  g_w1);
    cudaGetSymbolAddress((void**)&w2_p,  g_w2);

    // 0) Pre-round inputs to tf32 (removes all cvt from hot loops)
    round_tf32<<<512, 256>>>(x,     x_p,  (int)((size_t)M_TOT * DIM / 4));
    round_tf32<<<256, 256>>>(w_qkv, w1_p, (int)((size_t)DIM * D3 / 4));
    round_tf32<<<128, 256>>>(w_out, w2_p, (int)((size_t)DIM * DIM / 4));

    const int gemm_smem = (2 * GEMM_STAGE_A + 2 * GEMM_STAGE_B) * (int)sizeof(float);
    cudaFuncSetAttribute(gemm_bias_tc<1>, cudaFuncAttributeMaxDynamicSharedMemorySize, gemm_smem);
    cudaFuncSetAttribute(gemm_bias_tc<0>, cudaFuncAttributeMaxDynamicSharedMemorySize, gemm_smem);

    // 1) QKV projection (rounds output to tf32)
    gemm_bias_tc<1><<<dim3(D3 / 128, M_TOT / 128), 256, gemm_smem>>>(
        x_p, w1_p, b_qkv, qkv_p, M_TOT, D3, DIM);

    // 2) Causal flash attention
    cudaFuncSetAttribute(attn_fwd_tc, cudaFuncAttributeMaxDynamicSharedMemorySize, ATT_SMEM);
    attn_fwd_tc<<<dim3(SEQ / 128, NH, B_SZ), 256, ATT_SMEM>>>(qkv_p, att_p);

    // 3) Output projection (full fp32 output)
    gemm_bias_tc<0><<<dim3(DIM / 128, M_TOT / 128), 256, gemm_smem>>>(
        att_p, w2_p, b_out, out, M_TOT, DIM, DIM);
}